// round 15
// baseline (speedup 1.0000x reference)
#include <cuda_runtime.h>
#include <cuda_bf16.h>
#include <math.h>
#include <stdint.h>

#define TT 512
#define BB 16
#define HH 48
#define SS 4
#define OO 48
#define DD 768
#define NN 9216
#define MTOT 8192
#define NGROUP 192
#define CL 16
#define NC 32

__device__ __nv_bfloat16 g_emb16[MTOT * DD];
__device__ __nv_bfloat16 g_w16[NN * DD];
__device__ float g_val[MTOT * NGROUP];
__device__ float g_lep[MTOT * HH];
__device__ float g_elep[MTOT * HH];
__device__ float g_alpha[MTOT * HH];
__device__ float g_beta[MTOT * HH];
__device__ float g_partial[MTOT];
__device__ float g_lp[HH];
__device__ float g_log_trans[HH * HH];
__device__ float g_trans_prob[HH * HH];
__device__ float g_emiss_prob[SS * HH * OO];
__device__ float g_U[2 * BB * NC * HH * HH];
__device__ float g_ent[2 * BB * NC * HH];

__device__ __forceinline__ uint32_t smem_u32(const void* p) {
    uint32_t a;
    asm("{ .reg .u64 t; cvta.to.shared.u64 t, %1; cvt.u32.u64 %0, t; }" : "=r"(a) : "l"(p));
    return a;
}
__device__ __forceinline__ float fexp(float x) {
    if (x < -87.0f) return 0.0f;
    float t = x * 1.4426950408889634f;
    float n = rintf(t);
    float f = t - n;
    float p = 1.5403530393381609e-4f;
    p = fmaf(p, f, 1.3333558146428443e-3f);
    p = fmaf(p, f, 9.6181291076284772e-3f);
    p = fmaf(p, f, 5.5504108664821580e-2f);
    p = fmaf(p, f, 2.4022650695910072e-1f);
    p = fmaf(p, f, 6.9314718055994531e-1f);
    p = fmaf(p, f, 1.0f);
    int e = (int)n;
    if (e < -126) return 0.0f;
    if (e > 126) e = 126;
    return p * __int_as_float((e + 127) << 23);
}
__device__ __forceinline__ float blockSum256(float v, float* red) {
    int tid = threadIdx.x;
#pragma unroll
    for (int o = 16; o > 0; o >>= 1) v += __shfl_down_sync(0xffffffffu, v, o);
    __syncthreads();
    if ((tid & 31) == 0) red[tid >> 5] = v;
    __syncthreads();
    if (tid < 32) {
        float r = (tid < 8) ? red[tid] : 0.0f;
#pragma unroll
        for (int o = 4; o > 0; o >>= 1) r += __shfl_down_sync(0xffffffffu, r, o);
        if (tid == 0) red[0] = r;
    }
    __syncthreads();
    return red[0];
}

#define LDSM4(d, a) asm volatile("ldmatrix.sync.aligned.m8n8.x4.shared.b16 {%0,%1,%2,%3}, [%4];" \
    : "=r"((d)[0]), "=r"((d)[1]), "=r"((d)[2]), "=r"((d)[3]) : "r"(a))
#define MMAB(C, A, b0, b1) asm volatile( \
    "mma.sync.aligned.m16n8k16.row.col.f32.bf16.bf16.f32 {%0,%1,%2,%3}, {%4,%5,%6,%7}, {%8,%9}, {%0,%1,%2,%3};" \
    : "+f"((C)[0]), "+f"((C)[1]), "+f"((C)[2]), "+f"((C)[3]) \
    : "r"((A)[0]), "r"((A)[1]), "r"((A)[2]), "r"((A)[3]), "r"(b0), "r"(b1))

// ---------------- init ----------------
#define CONV_BLOCKS 13056
__global__ void __launch_bounds__(256) init_kernel(const float* __restrict__ emb,
                                                   const float* __restrict__ Wm,
                                                   const float* __restrict__ sp,
                                                   const float* __restrict__ ut,
                                                   const float* __restrict__ ue) {
    const int nA = MTOT * DD / 4, nW = NN * DD / 4;
    int blk = blockIdx.x, tid = threadIdx.x;
    if (blk < CONV_BLOCKS) {
        int i = blk * 256 + tid;
        if (i < nA) {
            float4 v = ((const float4*)emb)[i];
            ((__nv_bfloat162*)g_emb16)[i * 2] = __floats2bfloat162_rn(v.x, v.y);
            ((__nv_bfloat162*)g_emb16)[i * 2 + 1] = __floats2bfloat162_rn(v.z, v.w);
        } else if (i < nA + nW) {
            int j = i - nA;
            float4 v = ((const float4*)Wm)[j];
            ((__nv_bfloat162*)g_w16)[j * 2] = __floats2bfloat162_rn(v.x, v.y);
            ((__nv_bfloat162*)g_w16)[j * 2 + 1] = __floats2bfloat162_rn(v.z, v.w);
        }
        return;
    }
    if (tid < HH) {
        const float* row = ut + tid * HH;
        float m = row[0];
#pragma unroll
        for (int j = 1; j < HH; j++) m = fmaxf(m, row[j]);
        float s = 0.0f;
#pragma unroll
        for (int j = 0; j < HH; j++) s += fexp(row[j] - m);
        float ls = logf(s) + m;
#pragma unroll
        for (int j = 0; j < HH; j++) {
            float v = row[j] - ls;
            g_log_trans[tid * HH + j] = v;
            g_trans_prob[tid * HH + j] = fexp(v);
        }
    }
    if (tid < SS * HH) {
        const float* row = ue + tid * OO;
        float m = row[0];
#pragma unroll
        for (int j = 1; j < OO; j++) m = fmaxf(m, row[j]);
        float s = 0.0f;
#pragma unroll
        for (int j = 0; j < OO; j++) s += fexp(row[j] - m);
        float inv = 1.0f / s;
#pragma unroll
        for (int j = 0; j < OO; j++) g_emiss_prob[tid * OO + j] = fexp(row[j] - m) * inv;
    }
    if (tid == 0) {
        float m = sp[0];
        for (int j = 1; j < HH; j++) m = fmaxf(m, sp[j]);
        float s = 0.0f;
        for (int j = 0; j < HH; j++) s += fexp(sp[j] - m);
        float ls = logf(s) + m;
        for (int j = 0; j < HH; j++) g_lp[j] = sp[j] - ls;
    }
}

__global__ void dummy_kernel() {}

// ---------------- GEMM: 128x96, K=128/stage, 3-stage ring, 6 barrier iterations ----------------
#define STG2 57344                    /* A 2x16384 + B 2x12288 */
#define GEMM_SMEM (3 * STG2)          /* 172032 -> 1 CTA/SM */
__device__ __forceinline__ void cp_async16(uint32_t dst, const void* src) {
    asm volatile("cp.async.cg.shared.global [%0], [%1], 16;" ::
                 "r"(dst), "l"(__cvta_generic_to_global(src)));
}
__global__ void __launch_bounds__(256, 1) mma_fused_kernel(const float* __restrict__ bias,
                                                           const float* __restrict__ obs) {
    extern __shared__ char smem[];
    float* smf = (float*)smem;
    uint32_t sbase = smem_u32(smem);
    const int tid = threadIdx.x, wid = tid >> 5, lane = tid & 31;
    const int bn = blockIdx.x * 96, bm = blockIdx.y * 128;
    const int wm = (wid >> 1) * 32, gsel = wid & 1, wn = gsel * 48;
    const int sub = lane >> 3, l8 = lane & 7;
    const int a_row_in = (sub & 1) * 8 + l8, a_kb = (sub >> 1) * 16;
    const int b_row_in = (sub >> 1) * 8 + l8, b_kb = (sub & 1) * 16;
    uint32_t a_base[2], b_base[3];
    int a_xor[2], b_xor[3];
#pragma unroll
    for (int mi = 0; mi < 2; mi++) {
        int r = wm + mi * 16 + a_row_in;
        a_base[mi] = (uint32_t)(r * 128);
        a_xor[mi] = (r & 7) << 4;
    }
#pragma unroll
    for (int pi = 0; pi < 3; pi++) {
        int r = wn + pi * 16 + b_row_in;
        b_base[pi] = (uint32_t)(r * 128);
        b_xor[pi] = (r & 7) << 4;
    }
    float c[2][6][4];
#pragma unroll
    for (int mi = 0; mi < 2; mi++)
#pragma unroll
        for (int ni = 0; ni < 6; ni++)
#pragma unroll
            for (int q = 0; q < 4; q++) c[mi][ni][q] = 0.0f;

    // stage: [A0 16K][A1 16K][B0 12K][B1 12K] — two 64-wide k sub-tiles
    auto load_stage = [&](int kb2, int stage) {
        uint32_t base = sbase + (uint32_t)(stage * STG2);
#pragma unroll
        for (int h = 0; h < 2; h++) {
            int kb = kb2 * 2 + h;
            uint32_t adst = base + (uint32_t)(h * 16384);
            uint32_t bdst = base + 32768u + (uint32_t)(h * 12288);
#pragma unroll
            for (int p = 0; p < 4; p++) {
                int idx = tid + p * 256;
                int r = idx >> 3, cc = idx & 7;
                uint32_t off = (uint32_t)(r * 128 + cc * 16);
                off ^= (uint32_t)((r & 7) << 4);
                cp_async16(adst + off, g_emb16 + (size_t)(bm + r) * DD + kb * 64 + cc * 8);
            }
#pragma unroll
            for (int p = 0; p < 3; p++) {
                int idx = tid + p * 256;
                int r = idx >> 3, cc = idx & 7;
                uint32_t off = (uint32_t)(r * 128 + cc * 16);
                off ^= (uint32_t)((r & 7) << 4);
                cp_async16(bdst + off, g_w16 + (size_t)(bn + r) * DD + kb * 64 + cc * 8);
            }
        }
        asm volatile("cp.async.commit_group;" ::: "memory");
    };

    load_stage(0, 0);
    load_stage(1, 1);

    uint32_t fa[2][2][4], fb[2][6][2];
    int stg = 0;

    for (int kb2 = 0; kb2 < 6; kb2++) {
        if (kb2 < 5) asm volatile("cp.async.wait_group 1;" ::: "memory");
        else         asm volatile("cp.async.wait_group 0;" ::: "memory");
        __syncthreads();
        if (kb2 + 2 < 6) load_stage(kb2 + 2, (stg + 2) % 3);   // distinct from consuming stage

        uint32_t stb = sbase + (uint32_t)(stg * STG2);

        auto load_frags = [&](int ks, int pipe) {
            int half = ks >> 2, k4 = ks & 3;
            uint32_t abuf = stb + (uint32_t)(half * 16384);
            uint32_t bbuf = stb + 32768u + (uint32_t)(half * 12288);
#pragma unroll
            for (int mi = 0; mi < 2; mi++) {
                uint32_t addr = abuf + a_base[mi] + (uint32_t)((k4 * 32 + a_kb) ^ a_xor[mi]);
                LDSM4(fa[pipe][mi], addr);
            }
#pragma unroll
            for (int pi = 0; pi < 3; pi++) {
                uint32_t addr = bbuf + b_base[pi] + (uint32_t)((k4 * 32 + b_kb) ^ b_xor[pi]);
                uint32_t t4[4];
                LDSM4(t4, addr);
                fb[pipe][pi * 2][0] = t4[0]; fb[pipe][pi * 2][1] = t4[1];
                fb[pipe][pi * 2 + 1][0] = t4[2]; fb[pipe][pi * 2 + 1][1] = t4[3];
            }
        };

        load_frags(0, 0);
#pragma unroll
        for (int ks = 0; ks < 8; ks++) {
            int cur = ks & 1;
            if (ks < 7) load_frags(ks + 1, cur ^ 1);
#pragma unroll
            for (int mi = 0; mi < 2; mi++)
#pragma unroll
                for (int ni = 0; ni < 6; ni++)
                    MMAB(c[mi][ni], fa[cur][mi], fb[cur][ni][0], fb[cur][ni][1]);
        }
        stg = (stg + 1) % 3;
    }

    const int g0 = blockIdx.x * 2, s_src = g0 / HH, EPOFF = 6400;
    __syncthreads();
    for (int i = tid; i < 128 * 24; i += 256) {
        int r = i / 24, c2 = i - r * 24;
        float2 v = *(const float2*)&obs[((size_t)(bm + r) * SS + s_src) * OO + c2 * 2];
        *(float2*)&smf[r * 50 + c2 * 2] = v;
    }
    if (tid < 96) smf[EPOFF + tid] = g_emiss_prob[g0 * 48 + tid];
    __syncthreads();
    const int trow = lane >> 2, tcol = (lane & 3) * 2, ggl = g0 + gsel;
    float bx[6], by[6], epx[6], epy[6];
#pragma unroll
    for (int ni = 0; ni < 6; ni++) {
        float2 bv = *(const float2*)&bias[bn + wn + ni * 8 + tcol];
        bx[ni] = bv.x; by[ni] = bv.y;
        epx[ni] = smf[EPOFF + gsel * 48 + ni * 8 + tcol];
        epy[ni] = smf[EPOFF + gsel * 48 + ni * 8 + tcol + 1];
    }
#pragma unroll
    for (int mi = 0; mi < 2; mi++) {
#pragma unroll
        for (int half = 0; half < 2; half++) {
            int rt = wm + mi * 16 + half * 8 + trow;
            float vx[6], vy[6], mx = -3.0e38f;
#pragma unroll
            for (int ni = 0; ni < 6; ni++) {
                vx[ni] = c[mi][ni][half * 2] + bx[ni];
                vy[ni] = c[mi][ni][half * 2 + 1] + by[ni];
                mx = fmaxf(mx, fmaxf(vx[ni], vy[ni]));
            }
            mx = fmaxf(mx, __shfl_xor_sync(0xffffffffu, mx, 1));
            mx = fmaxf(mx, __shfl_xor_sync(0xffffffffu, mx, 2));
            float den = 0.0f, dot = 0.0f, eo = 0.0f;
            const float* obr = &smf[rt * 50];
#pragma unroll
            for (int ni = 0; ni < 6; ni++) {
                float obx = obr[ni * 8 + tcol], oby = obr[ni * 8 + tcol + 1];
                float ex = fexp(vx[ni] - mx), ey = fexp(vy[ni] - mx);
                den += ex + ey;
                dot = fmaf(ex, obx, dot); dot = fmaf(ey, oby, dot);
                eo = fmaf(epx[ni], obx, eo); eo = fmaf(epy[ni], oby, eo);
            }
#pragma unroll
            for (int m = 1; m <= 2; m <<= 1) {
                den += __shfl_xor_sync(0xffffffffu, den, m);
                dot += __shfl_xor_sync(0xffffffffu, dot, m);
                eo  += __shfl_xor_sync(0xffffffffu, eo, m);
            }
            if ((lane & 3) == 0)
                g_val[(size_t)(bm + rt) * NGROUP + ggl] = 0.5f * eo + 0.5f * (dot / den);
        }
    }
}

__global__ void __launch_bounds__(256) combine_kernel() {
    int idx = blockIdx.x * 256 + threadIdx.x;
    if (idx >= MTOT * HH) return;
    int bt = idx / HH, h = idx - bt * HH;
    const float* v = g_val + (size_t)bt * NGROUP + h;
    float p = v[0] * v[48] * v[96] * v[144];
    g_elep[idx] = p;
    g_lep[idx] = logf(p);
}

// ---------------- pass A: HMMA chunk products, split-bf16 (validated) ----------------
__global__ void __launch_bounds__(32) passA_kernel() {
    __shared__ __align__(16) __nv_bfloat16 Ahs[HH * 64], Als[HH * 64];
    __shared__ __align__(16) __nv_bfloat16 Bhs[HH * 64], Bls[HH * 64];
    __shared__ float ech[CL][HH];
    const unsigned F = 0xffffffffu;
    int lane = threadIdx.x;
    int blk = blockIdx.x, dir = blk >> 9, b = (blk >> 5) & 15, c = blk & 31;
    int t_lo, t_hi, e0;
    if (dir == 0) { t_lo = (c == 0) ? 1 : c * CL; t_hi = c * CL + CL - 1; e0 = t_lo; }
    else { t_lo = c * CL; t_hi = (c == NC - 1) ? TT - 2 : c * CL + CL - 1; e0 = t_lo + 1; }
    int ns = t_hi - t_lo + 1;
    const float* es = g_elep + (size_t)(b * TT + e0) * HH;
    for (int x = lane; x < ns * HH; x += 32) ech[x / HH][x % HH] = es[x];
    __syncwarp(F);
    for (int x = lane; x < HH * HH; x += 32) {
        int i = x / HH, k = x - i * HH;
        float tv = (dir == 0) ? g_trans_prob[k * HH + i] : g_trans_prob[i * HH + k];
        __nv_bfloat16 h = __float2bfloat16(tv);
        __nv_bfloat16 l = __float2bfloat16(tv - __bfloat162float(h));
        uint32_t off = (uint32_t)(i * 128 + k * 2);
        off ^= (off >> 3) & 0x70;
        *(__nv_bfloat16*)((char*)Ahs + off) = h;
        *(__nv_bfloat16*)((char*)Als + off) = l;
    }
    for (int x = lane; x < HH * HH; x += 32) {
        int j = x / HH, i = x - j * HH;
        float v;
        if (dir == 0) v = g_trans_prob[j * HH + i] * ech[0][i];
        else          v = g_trans_prob[i * HH + j] * ech[ns - 1][j] * ech[ns - 2][i];
        __nv_bfloat16 h = __float2bfloat16(v);
        __nv_bfloat16 l = __float2bfloat16(v - __bfloat162float(h));
        uint32_t off = (uint32_t)(j * 128 + i * 2);
        off ^= (off >> 3) & 0x70;
        *(__nv_bfloat16*)((char*)Bhs + off) = h;
        *(__nv_bfloat16*)((char*)Bls + off) = l;
    }
    __syncwarp(F);

    uint32_t ah_b = smem_u32(Ahs), al_b = smem_u32(Als);
    uint32_t bh_b = smem_u32(Bhs), bl_b = smem_u32(Bls);
    const int sub = lane >> 3, l8 = lane & 7;
    const int ar = (sub & 1) * 8 + l8, akb = (sub >> 1) * 16;
    const int br = (sub >> 1) * 8 + l8, bkb = (sub & 1) * 16;
    const int g = lane >> 2, tc = (lane & 3) * 2;

    uint32_t fah[3][3][4], fal[3][3][4];
#pragma unroll
    for (int mi = 0; mi < 3; mi++)
#pragma unroll
        for (int kk = 0; kk < 3; kk++) {
            int r = mi * 16 + ar;
            uint32_t off = (uint32_t)(r * 128) + (uint32_t)((kk * 32 + akb) ^ ((r & 7) << 4));
            LDSM4(fah[mi][kk], ah_b + off);
            LDSM4(fal[mi][kk], al_b + off);
        }

    for (int s = 1; s < ns; s++) {
        float cc[3][6][4];
#pragma unroll
        for (int mi = 0; mi < 3; mi++)
#pragma unroll
            for (int ni = 0; ni < 6; ni++)
#pragma unroll
                for (int q = 0; q < 4; q++) cc[mi][ni][q] = 0.0f;
#pragma unroll
        for (int kk = 0; kk < 3; kk++) {
            uint32_t gh[3][4], gl[3][4];
#pragma unroll
            for (int pi = 0; pi < 3; pi++) {
                int r = pi * 16 + br;
                uint32_t off = (uint32_t)(r * 128) + (uint32_t)((kk * 32 + bkb) ^ ((r & 7) << 4));
                LDSM4(gh[pi], bh_b + off);
                LDSM4(gl[pi], bl_b + off);
            }
#pragma unroll
            for (int mi = 0; mi < 3; mi++)
#pragma unroll
                for (int pi = 0; pi < 3; pi++) {
                    MMAB(cc[mi][2 * pi],     fah[mi][kk], gh[pi][0], gh[pi][1]);
                    MMAB(cc[mi][2 * pi + 1], fah[mi][kk], gh[pi][2], gh[pi][3]);
                    MMAB(cc[mi][2 * pi],     fah[mi][kk], gl[pi][0], gl[pi][1]);
                    MMAB(cc[mi][2 * pi + 1], fah[mi][kk], gl[pi][2], gl[pi][3]);
                    MMAB(cc[mi][2 * pi],     fal[mi][kk], gh[pi][0], gh[pi][1]);
                    MMAB(cc[mi][2 * pi + 1], fal[mi][kk], gh[pi][2], gh[pi][3]);
                }
        }
        int sid = (dir == 0) ? s : (ns - 2 - s);
        float m = 0.0f;
#pragma unroll
        for (int mi = 0; mi < 3; mi++) {
            float slo = 1.0f, shi = 1.0f;
            if (sid >= 0) { slo = ech[sid][mi * 16 + g]; shi = ech[sid][mi * 16 + g + 8]; }
#pragma unroll
            for (int ni = 0; ni < 6; ni++) {
                cc[mi][ni][0] *= slo; cc[mi][ni][1] *= slo;
                cc[mi][ni][2] *= shi; cc[mi][ni][3] *= shi;
                m = fmaxf(m, fmaxf(fmaxf(fabsf(cc[mi][ni][0]), fabsf(cc[mi][ni][1])),
                                   fmaxf(fabsf(cc[mi][ni][2]), fabsf(cc[mi][ni][3]))));
            }
        }
#pragma unroll
        for (int o = 16; o > 0; o >>= 1) m = fmaxf(m, __shfl_xor_sync(F, m, o));
        float rn = 1.0f / m;
        if (s < ns - 1) {
#pragma unroll
            for (int mi = 0; mi < 3; mi++)
#pragma unroll
                for (int ni = 0; ni < 6; ni++)
#pragma unroll
                    for (int q = 0; q < 4; q++) {
                        int ri = mi * 16 + g + ((q >> 1) ? 8 : 0);
                        int cj = ni * 8 + tc + (q & 1);
                        float v = cc[mi][ni][q] * rn;
                        __nv_bfloat16 h = __float2bfloat16(v);
                        __nv_bfloat16 l = __float2bfloat16(v - __bfloat162float(h));
                        uint32_t off = (uint32_t)(cj * 128 + ri * 2);
                        off ^= (off >> 3) & 0x70;
                        *(__nv_bfloat16*)((char*)Bhs + off) = h;
                        *(__nv_bfloat16*)((char*)Bls + off) = l;
                    }
            __syncwarp(F);
        } else {
            float* dst = g_U + (size_t)blk * (HH * HH);
#pragma unroll
            for (int mi = 0; mi < 3; mi++)
#pragma unroll
                for (int ni = 0; ni < 6; ni++) {
                    int r0 = mi * 16 + g, cj = ni * 8 + tc;
                    float2 v0 = {cc[mi][ni][0] * rn, cc[mi][ni][1] * rn};
                    float2 v1 = {cc[mi][ni][2] * rn, cc[mi][ni][3] * rn};
                    *(float2*)&dst[r0 * HH + cj] = v0;
                    *(float2*)&dst[(r0 + 8) * HH + cj] = v1;
                }
        }
    }
}

// ---------------- pass B (validated) ----------------
__global__ void __launch_bounds__(64) passB_kernel() {
    __shared__ __align__(16) float v[HH];
    __shared__ float nv[HH];
    __shared__ float rn;
    int tid = threadIdx.x;
    int dir = blockIdx.x >> 4, b = blockIdx.x & 15;
    bool act = tid < HH;
    float* ent = g_ent + ((size_t)(dir * BB + b) * NC) * HH;
    if (dir == 0) {
        if (act) v[tid] = fexp(g_lp[tid]) * g_elep[(size_t)(b * TT) * HH + tid];
        __syncthreads();
        if (tid == 0) {
            float m = 0;
            for (int k = 0; k < HH; k++) m = fmaxf(m, v[k]);
            rn = 1.0f / m;
        }
        __syncthreads();
        if (act) { v[tid] *= rn; ent[tid] = v[tid]; }
        __syncthreads();
        for (int c = 0; c < NC - 1; c++) {
            const float* U = g_U + (size_t)(b * NC + c) * (HH * HH);
            float s = 0.0f;
            if (act) {
                const float4* u4 = (const float4*)(U + tid * HH);
                const float4* v4 = (const float4*)v;
#pragma unroll
                for (int k = 0; k < 12; k++) {
                    float4 u = u4[k], w = v4[k];
                    s = fmaf(u.x, w.x, s); s = fmaf(u.y, w.y, s);
                    s = fmaf(u.z, w.z, s); s = fmaf(u.w, w.w, s);
                }
            }
            __syncthreads();
            if (act) nv[tid] = s;
            __syncthreads();
            if (tid == 0) {
                float m = 0;
                for (int k = 0; k < HH; k++) m = fmaxf(m, fabsf(nv[k]));
                rn = 1.0f / m;
            }
            __syncthreads();
            if (act) { float x = nv[tid] * rn; v[tid] = x; ent[(size_t)(c + 1) * HH + tid] = x; }
            __syncthreads();
        }
    } else {
        if (act) { v[tid] = 1.0f; ent[(size_t)(NC - 1) * HH + tid] = 1.0f; }
        __syncthreads();
        for (int c = NC - 2; c >= 0; c--) {
            const float* U = g_U + (size_t)(512 + b * NC + (c + 1)) * (HH * HH);
            float s = 0.0f;
            if (act) {
                const float4* u4 = (const float4*)(U + tid * HH);
                const float4* v4 = (const float4*)v;
#pragma unroll
                for (int k = 0; k < 12; k++) {
                    float4 u = u4[k], w = v4[k];
                    s = fmaf(u.x, w.x, s); s = fmaf(u.y, w.y, s);
                    s = fmaf(u.z, w.z, s); s = fmaf(u.w, w.w, s);
                }
            }
            __syncthreads();
            if (act) nv[tid] = s;
            __syncthreads();
            if (tid == 0) {
                float m = 0;
                for (int k = 0; k < HH; k++) m = fmaxf(m, fabsf(nv[k]));
                rn = 1.0f / m;
            }
            __syncthreads();
            if (act) { float x = nv[tid] * rn; v[tid] = x; ent[(size_t)c * HH + tid] = x; }
            __syncthreads();
        }
    }
}

// ---------------- pass C (validated) ----------------
__global__ void __launch_bounds__(64) passC_kernel() {
    __shared__ __align__(16) float cur[HH];
    __shared__ float red2[2];
    const unsigned FULL = 0xffffffffu;
    int tid = threadIdx.x, wid = tid >> 5;
    int blk = blockIdx.x, dir = blk >> 9, b = (blk >> 5) & 15, c = blk & 31;
    bool act = tid < HH;
    float Tc[HH];
    if (act) {
#pragma unroll
        for (int k = 0; k < HH; k++)
            Tc[k] = (dir == 0) ? g_trans_prob[k * HH + tid] : g_trans_prob[tid * HH + k];
    }
    const float* ent = g_ent + ((size_t)(dir * BB + b) * NC + c) * HH;
    float own = act ? ent[tid] : 0.0f;
    if (dir == 0) {
        int tstart = (c == 0) ? 1 : c * CL;
        int tend = c * CL + CL - 1;
        if (c == 0 && act) g_alpha[(size_t)(b * TT) * HH + tid] = own;
        for (int t = tstart; t <= tend; t++) {
            if (act) cur[tid] = own;
            __syncthreads();
            float a = 0.0f;
            if (act) {
                const float4* v4 = (const float4*)cur;
                float p0 = 0, p1 = 0, p2 = 0, p3 = 0;
#pragma unroll
                for (int k = 0; k < 12; k++) {
                    float4 u = v4[k];
                    p0 = fmaf(u.x, Tc[4 * k + 0], p0);
                    p1 = fmaf(u.y, Tc[4 * k + 1], p1);
                    p2 = fmaf(u.z, Tc[4 * k + 2], p2);
                    p3 = fmaf(u.w, Tc[4 * k + 3], p3);
                }
                float el = g_elep[(size_t)(b * TT + t) * HH + tid];
                a = ((p0 + p1) + (p2 + p3)) * el;
                g_alpha[(size_t)(b * TT + t) * HH + tid] = a;
            }
            if ((t & 1) == 0) {
                float s = a;
#pragma unroll
                for (int o = 16; o > 0; o >>= 1) s += __shfl_xor_sync(FULL, s, o);
                if ((tid & 31) == 0) red2[wid] = s;
                __syncthreads();
                a *= 1.0f / (red2[0] + red2[1]);
            }
            own = a;
            __syncthreads();
        }
    } else {
        int thi = (c == NC - 1) ? TT - 2 : c * CL + CL - 1;
        int tlo = c * CL;
        if (c == NC - 1 && act) g_beta[(size_t)(b * TT + TT - 1) * HH + tid] = own;
        for (int t = thi; t >= tlo; t--) {
            if (act) {
                float el = g_elep[(size_t)(b * TT + t + 1) * HH + tid];
                cur[tid] = el * own;
            }
            __syncthreads();
            float a = 0.0f;
            if (act) {
                const float4* v4 = (const float4*)cur;
                float p0 = 0, p1 = 0, p2 = 0, p3 = 0;
#pragma unroll
                for (int k = 0; k < 12; k++) {
                    float4 u = v4[k];
                    p0 = fmaf(u.x, Tc[4 * k + 0], p0);
                    p1 = fmaf(u.y, Tc[4 * k + 1], p1);
                    p2 = fmaf(u.z, Tc[4 * k + 2], p2);
                    p3 = fmaf(u.w, Tc[4 * k + 3], p3);
                }
                a = (p0 + p1) + (p2 + p3);
                g_beta[(size_t)(b * TT + t) * HH + tid] = a;
            }
            if ((t & 1) == 0) {
                float s = a;
#pragma unroll
                for (int o = 16; o > 0; o >>= 1) s += __shfl_xor_sync(FULL, s, o);
                if ((tid & 31) == 0) red2[wid] = s;
                __syncthreads();
                a *= 1.0f / (red2[0] + red2[1]);
            }
            own = a;
            __syncthreads();
        }
    }
}

// ---------------- final: 4 t per block ----------------
__global__ void __launch_bounds__(256) final_kernel(const int* __restrict__ seq) {
    __shared__ float lt[HH * HH];
    __shared__ float tp[HH * HH];
    __shared__ float sA[HH], sU[HH], sG[HH], sL[HH];
    __shared__ float red[32];
    int tid = threadIdx.x;
    int b = blockIdx.x >> 7;
    int t0 = (blockIdx.x & 127) * 4;
    int len = seq[b];

    for (int i = tid; i < HH * HH; i += 256) {
        lt[i] = g_log_trans[i];
        tp[i] = g_trans_prob[i];
    }
    __syncthreads();

    for (int q4 = 0; q4 < 4; q4++) {
        int t = t0 + q4;
        int bt = b * TT + t;
        if (t >= len) {
            if (tid == 0) g_partial[bt] = 0.0f;
            continue;
        }
        bool do_xi = (t >= 1);
        if (tid < HH) {
            int tb = (t + TT - len) & (TT - 1);
            float br = g_beta[(size_t)(b * TT + tb) * HH + tid];
            float at = g_alpha[(size_t)bt * HH + tid];
            float lpv = g_lep[(size_t)bt * HH + tid];
            float el = g_elep[(size_t)bt * HH + tid];
            sG[tid] = at * br;
            sU[tid] = el * br;
            sL[tid] = lpv;
            sA[tid] = (t > 0) ? g_alpha[(size_t)(bt - 1) * HH + tid] : 0.0f;
        }
        __syncthreads();

        float e = (tid < HH) ? sG[tid] : 0.0f;
        float Z = blockSum256(e, red);
        float E = blockSum256(e * ((tid < HH) ? sL[tid] : 0.0f), red);
        float total = E / Z;
        if (t == 0) {
            float P = blockSum256(e * ((tid < HH) ? g_lp[tid] : 0.0f), red);
            total += P / Z;
        }
        if (do_xi) {
            float z = 0.0f, w = 0.0f;
            for (int idx = tid; idx < HH * HH; idx += 256) {
                int i = idx / HH, j = idx - i * HH;
                float val = tp[idx] * sA[i] * sU[j];
                z += val;
                w = fmaf(val, lt[idx], w);
            }
            float Z2 = blockSum256(z, red);
            float W2 = blockSum256(w, red);
            total += W2 / Z2;
        }
        if (tid == 0) g_partial[bt] = total;
        __syncthreads();
    }
}

__global__ void __launch_bounds__(256) reduce_kernel(float* __restrict__ out) {
    __shared__ float red[256];
    int tid = threadIdx.x;
    float s = 0.0f;
    for (int i = tid; i < MTOT; i += 256) s += g_partial[i];
    red[tid] = s;
    __syncthreads();
    for (int off = 128; off > 0; off >>= 1) {
        if (tid < off) red[tid] += red[tid + off];
        __syncthreads();
    }
    if (tid == 0) out[0] = red[0] * (1.0f / (float)BB);
}

extern "C" void kernel_launch(void* const* d_in, const int* in_sizes, int n_in,
                              void* d_out, int out_size) {
    const float* emb  = (const float*)d_in[0];
    const float* obs  = (const float*)d_in[1];
    const float* sp   = (const float*)d_in[2];
    const float* ut   = (const float*)d_in[3];
    const float* ue   = (const float*)d_in[4];
    const float* Wm   = (const float*)d_in[5];
    const float* bias = (const float*)d_in[6];
    const int*   seq  = (const int*)d_in[7];
    float* out = (float*)d_out;

    cudaFuncSetAttribute(mma_fused_kernel, cudaFuncAttributeMaxDynamicSharedMemorySize, GEMM_SMEM);

    init_kernel<<<CONV_BLOCKS + 1, 256>>>(emb, Wm, sp, ut, ue);   // 1
    dummy_kernel<<<1, 32>>>();                                    // 2
    dummy_kernel<<<1, 32>>>();                                    // 3
    dim3 ggrid(NN / 96, MTOT / 128);
    mma_fused_kernel<<<ggrid, 256, GEMM_SMEM>>>(bias, obs);       // 4 <- ncu window
    combine_kernel<<<(MTOT * HH + 255) / 256, 256>>>();           // 5
    passA_kernel<<<1024, 32>>>();                                 // 6
    passB_kernel<<<32, 64>>>();                                   // 7
    passC_kernel<<<1024, 64>>>();                                 // 8
    final_kernel<<<MTOT / 4, 256>>>(seq);                         // 9
    reduce_kernel<<<1, 256>>>(out);                               // 10
}

// round 16
// speedup vs baseline: 1.3844x; 1.3844x over previous
#include <cuda_runtime.h>
#include <cuda_bf16.h>
#include <math.h>
#include <stdint.h>

#define TT 512
#define BB 16
#define HH 48
#define SS 4
#define OO 48
#define DD 768
#define NN 9216
#define MTOT 8192
#define NGROUP 192
#define CL 16
#define NC 32

__device__ __nv_bfloat16 g_emb16[MTOT * DD];
__device__ __nv_bfloat16 g_w16[NN * DD];
__device__ float g_val[MTOT * NGROUP];
__device__ float g_lep[MTOT * HH];
__device__ float g_elep[MTOT * HH];
__device__ float g_alpha[MTOT * HH];
__device__ float g_beta[MTOT * HH];
__device__ float g_partial[MTOT];
__device__ float g_lp[HH];
__device__ float g_log_trans[HH * HH];
__device__ float g_trans_prob[HH * HH];
__device__ float g_emiss_prob[SS * HH * OO];
__device__ float g_U[2 * BB * NC * HH * HH];
__device__ float g_ent[2 * BB * NC * HH];

__device__ __forceinline__ uint32_t smem_u32(const void* p) {
    uint32_t a;
    asm("{ .reg .u64 t; cvta.to.shared.u64 t, %1; cvt.u32.u64 %0, t; }" : "=r"(a) : "l"(p));
    return a;
}
__device__ __forceinline__ float fexp(float x) {
    if (x < -87.0f) return 0.0f;
    float t = x * 1.4426950408889634f;
    float n = rintf(t);
    float f = t - n;
    float p = 1.5403530393381609e-4f;
    p = fmaf(p, f, 1.3333558146428443e-3f);
    p = fmaf(p, f, 9.6181291076284772e-3f);
    p = fmaf(p, f, 5.5504108664821580e-2f);
    p = fmaf(p, f, 2.4022650695910072e-1f);
    p = fmaf(p, f, 6.9314718055994531e-1f);
    p = fmaf(p, f, 1.0f);
    int e = (int)n;
    if (e < -126) return 0.0f;
    if (e > 126) e = 126;
    return p * __int_as_float((e + 127) << 23);
}
__device__ __forceinline__ float blockSum256(float v, float* red) {
    int tid = threadIdx.x;
#pragma unroll
    for (int o = 16; o > 0; o >>= 1) v += __shfl_down_sync(0xffffffffu, v, o);
    __syncthreads();
    if ((tid & 31) == 0) red[tid >> 5] = v;
    __syncthreads();
    if (tid < 32) {
        float r = (tid < 8) ? red[tid] : 0.0f;
#pragma unroll
        for (int o = 4; o > 0; o >>= 1) r += __shfl_down_sync(0xffffffffu, r, o);
        if (tid == 0) red[0] = r;
    }
    __syncthreads();
    return red[0];
}

#define LDSM4(d, a) asm volatile("ldmatrix.sync.aligned.m8n8.x4.shared.b16 {%0,%1,%2,%3}, [%4];" \
    : "=r"((d)[0]), "=r"((d)[1]), "=r"((d)[2]), "=r"((d)[3]) : "r"(a))
#define MMAB(C, A, b0, b1) asm volatile( \
    "mma.sync.aligned.m16n8k16.row.col.f32.bf16.bf16.f32 {%0,%1,%2,%3}, {%4,%5,%6,%7}, {%8,%9}, {%0,%1,%2,%3};" \
    : "+f"((C)[0]), "+f"((C)[1]), "+f"((C)[2]), "+f"((C)[3]) \
    : "r"((A)[0]), "r"((A)[1]), "r"((A)[2]), "r"((A)[3]), "r"(b0), "r"(b1))

// ---------------- init ----------------
#define CONV_BLOCKS 13056
__global__ void __launch_bounds__(256) init_kernel(const float* __restrict__ emb,
                                                   const float* __restrict__ Wm,
                                                   const float* __restrict__ sp,
                                                   const float* __restrict__ ut,
                                                   const float* __restrict__ ue) {
    const int nA = MTOT * DD / 4, nW = NN * DD / 4;
    int blk = blockIdx.x, tid = threadIdx.x;
    if (blk < CONV_BLOCKS) {
        int i = blk * 256 + tid;
        if (i < nA) {
            float4 v = ((const float4*)emb)[i];
            ((__nv_bfloat162*)g_emb16)[i * 2] = __floats2bfloat162_rn(v.x, v.y);
            ((__nv_bfloat162*)g_emb16)[i * 2 + 1] = __floats2bfloat162_rn(v.z, v.w);
        } else if (i < nA + nW) {
            int j = i - nA;
            float4 v = ((const float4*)Wm)[j];
            ((__nv_bfloat162*)g_w16)[j * 2] = __floats2bfloat162_rn(v.x, v.y);
            ((__nv_bfloat162*)g_w16)[j * 2 + 1] = __floats2bfloat162_rn(v.z, v.w);
        }
        return;
    }
    if (tid < HH) {
        const float* row = ut + tid * HH;
        float m = row[0];
#pragma unroll
        for (int j = 1; j < HH; j++) m = fmaxf(m, row[j]);
        float s = 0.0f;
#pragma unroll
        for (int j = 0; j < HH; j++) s += fexp(row[j] - m);
        float ls = logf(s) + m;
#pragma unroll
        for (int j = 0; j < HH; j++) {
            float v = row[j] - ls;
            g_log_trans[tid * HH + j] = v;
            g_trans_prob[tid * HH + j] = fexp(v);
        }
    }
    if (tid < SS * HH) {
        const float* row = ue + tid * OO;
        float m = row[0];
#pragma unroll
        for (int j = 1; j < OO; j++) m = fmaxf(m, row[j]);
        float s = 0.0f;
#pragma unroll
        for (int j = 0; j < OO; j++) s += fexp(row[j] - m);
        float inv = 1.0f / s;
#pragma unroll
        for (int j = 0; j < OO; j++) g_emiss_prob[tid * OO + j] = fexp(row[j] - m) * inv;
    }
    if (tid == 0) {
        float m = sp[0];
        for (int j = 1; j < HH; j++) m = fmaxf(m, sp[j]);
        float s = 0.0f;
        for (int j = 0; j < HH; j++) s += fexp(sp[j] - m);
        float ls = logf(s) + m;
        for (int j = 0; j < HH; j++) g_lp[j] = sp[j] - ls;
    }
}

// ---------------- GEMM: 128x96, 4-stage K=64, 2 CTAs/SM (validated 417us) ----------------
#define STAGE_BYTES 28672
#define GEMM_SMEM (4 * STAGE_BYTES)
__device__ __forceinline__ void cp_async16(uint32_t dst, const void* src) {
    asm volatile("cp.async.cg.shared.global [%0], [%1], 16;" ::
                 "r"(dst), "l"(__cvta_generic_to_global(src)));
}
__global__ void __launch_bounds__(256, 2) mma_fused_kernel(const float* __restrict__ bias,
                                                           const float* __restrict__ obs) {
    extern __shared__ char smem[];
    float* smf = (float*)smem;
    uint32_t sbase = smem_u32(smem);
    const int tid = threadIdx.x, wid = tid >> 5, lane = tid & 31;
    const int bn = blockIdx.x * 96, bm = blockIdx.y * 128;
    const int wm = (wid >> 1) * 32, gsel = wid & 1, wn = gsel * 48;
    const int sub = lane >> 3, l8 = lane & 7;
    const int a_row_in = (sub & 1) * 8 + l8, a_kb = (sub >> 1) * 16;
    const int b_row_in = (sub >> 1) * 8 + l8, b_kb = (sub & 1) * 16;
    uint32_t a_base[2], b_base[3];
    int a_xor[2], b_xor[3];
#pragma unroll
    for (int mi = 0; mi < 2; mi++) {
        int r = wm + mi * 16 + a_row_in;
        a_base[mi] = (uint32_t)(r * 128);
        a_xor[mi] = (r & 7) << 4;
    }
#pragma unroll
    for (int pi = 0; pi < 3; pi++) {
        int r = wn + pi * 16 + b_row_in;
        b_base[pi] = (uint32_t)(r * 128);
        b_xor[pi] = (r & 7) << 4;
    }
    float c[2][6][4];
#pragma unroll
    for (int mi = 0; mi < 2; mi++)
#pragma unroll
        for (int ni = 0; ni < 6; ni++)
#pragma unroll
            for (int q = 0; q < 4; q++) c[mi][ni][q] = 0.0f;
    auto load_tiles = [&](int kb, int stage) {
        uint32_t adst = sbase + (uint32_t)(stage * STAGE_BYTES);
        uint32_t bdst = adst + 16384u;
#pragma unroll
        for (int p = 0; p < 4; p++) {
            int idx = tid + p * 256;
            int r = idx >> 3, cc = idx & 7;
            uint32_t off = (uint32_t)(r * 128 + cc * 16);
            off ^= (uint32_t)((r & 7) << 4);
            cp_async16(adst + off, g_emb16 + (size_t)(bm + r) * DD + kb * 64 + cc * 8);
        }
#pragma unroll
        for (int p = 0; p < 3; p++) {
            int idx = tid + p * 256;
            int r = idx >> 3, cc = idx & 7;
            uint32_t off = (uint32_t)(r * 128 + cc * 16);
            off ^= (uint32_t)((r & 7) << 4);
            cp_async16(bdst + off, g_w16 + (size_t)(bn + r) * DD + kb * 64 + cc * 8);
        }
        asm volatile("cp.async.commit_group;" ::: "memory");
    };
    load_tiles(0, 0); load_tiles(1, 1); load_tiles(2, 2);
    uint32_t fa[2][2][4], fb[2][6][2];
    for (int kb = 0; kb < 12; kb++) {
        if (kb <= 9)       asm volatile("cp.async.wait_group 2;" ::: "memory");
        else if (kb == 10) asm volatile("cp.async.wait_group 1;" ::: "memory");
        else               asm volatile("cp.async.wait_group 0;" ::: "memory");
        __syncthreads();
        if (kb + 3 < 12) load_tiles(kb + 3, (kb + 3) & 3);
        uint32_t abuf = sbase + (uint32_t)((kb & 3) * STAGE_BYTES);
        uint32_t bbuf = abuf + 16384u;
        auto load_frags = [&](int ks, int pipe) {
#pragma unroll
            for (int mi = 0; mi < 2; mi++) {
                uint32_t addr = abuf + a_base[mi] + (uint32_t)((ks * 32 + a_kb) ^ a_xor[mi]);
                LDSM4(fa[pipe][mi], addr);
            }
#pragma unroll
            for (int pi = 0; pi < 3; pi++) {
                uint32_t addr = bbuf + b_base[pi] + (uint32_t)((ks * 32 + b_kb) ^ b_xor[pi]);
                uint32_t t4[4];
                LDSM4(t4, addr);
                fb[pipe][pi * 2][0] = t4[0]; fb[pipe][pi * 2][1] = t4[1];
                fb[pipe][pi * 2 + 1][0] = t4[2]; fb[pipe][pi * 2 + 1][1] = t4[3];
            }
        };
        load_frags(0, 0);
#pragma unroll
        for (int ks = 0; ks < 4; ks++) {
            int cur = ks & 1;
            if (ks < 3) load_frags(ks + 1, cur ^ 1);
#pragma unroll
            for (int mi = 0; mi < 2; mi++)
#pragma unroll
                for (int ni = 0; ni < 6; ni++)
                    MMAB(c[mi][ni], fa[cur][mi], fb[cur][ni][0], fb[cur][ni][1]);
        }
    }
    const int g0 = blockIdx.x * 2, s_src = g0 / HH, EPOFF = 6400;
    __syncthreads();
    for (int i = tid; i < 128 * 24; i += 256) {
        int r = i / 24, c2 = i - r * 24;
        float2 v = *(const float2*)&obs[((size_t)(bm + r) * SS + s_src) * OO + c2 * 2];
        *(float2*)&smf[r * 50 + c2 * 2] = v;
    }
    if (tid < 96) smf[EPOFF + tid] = g_emiss_prob[g0 * 48 + tid];
    __syncthreads();
    const int trow = lane >> 2, tcol = (lane & 3) * 2, ggl = g0 + gsel;
    float bx[6], by[6], epx[6], epy[6];
#pragma unroll
    for (int ni = 0; ni < 6; ni++) {
        float2 bv = *(const float2*)&bias[bn + wn + ni * 8 + tcol];
        bx[ni] = bv.x; by[ni] = bv.y;
        epx[ni] = smf[EPOFF + gsel * 48 + ni * 8 + tcol];
        epy[ni] = smf[EPOFF + gsel * 48 + ni * 8 + tcol + 1];
    }
#pragma unroll
    for (int mi = 0; mi < 2; mi++) {
#pragma unroll
        for (int half = 0; half < 2; half++) {
            int rt = wm + mi * 16 + half * 8 + trow;
            float vx[6], vy[6], mx = -3.0e38f;
#pragma unroll
            for (int ni = 0; ni < 6; ni++) {
                vx[ni] = c[mi][ni][half * 2] + bx[ni];
                vy[ni] = c[mi][ni][half * 2 + 1] + by[ni];
                mx = fmaxf(mx, fmaxf(vx[ni], vy[ni]));
            }
            mx = fmaxf(mx, __shfl_xor_sync(0xffffffffu, mx, 1));
            mx = fmaxf(mx, __shfl_xor_sync(0xffffffffu, mx, 2));
            float den = 0.0f, dot = 0.0f, eo = 0.0f;
            const float* obr = &smf[rt * 50];
#pragma unroll
            for (int ni = 0; ni < 6; ni++) {
                float obx = obr[ni * 8 + tcol], oby = obr[ni * 8 + tcol + 1];
                float ex = fexp(vx[ni] - mx), ey = fexp(vy[ni] - mx);
                den += ex + ey;
                dot = fmaf(ex, obx, dot); dot = fmaf(ey, oby, dot);
                eo = fmaf(epx[ni], obx, eo); eo = fmaf(epy[ni], oby, eo);
            }
#pragma unroll
            for (int m = 1; m <= 2; m <<= 1) {
                den += __shfl_xor_sync(0xffffffffu, den, m);
                dot += __shfl_xor_sync(0xffffffffu, dot, m);
                eo  += __shfl_xor_sync(0xffffffffu, eo, m);
            }
            if ((lane & 3) == 0)
                g_val[(size_t)(bm + rt) * NGROUP + ggl] = 0.5f * eo + 0.5f * (dot / den);
        }
    }
}

__global__ void __launch_bounds__(256) combine_kernel() {
    int idx = blockIdx.x * 256 + threadIdx.x;
    if (idx >= MTOT * HH) return;
    int bt = idx / HH, h = idx - bt * HH;
    const float* v = g_val + (size_t)bt * NGROUP + h;
    float p = v[0] * v[48] * v[96] * v[144];
    g_elep[idx] = p;
    g_lep[idx] = logf(p);
}

// ---------------- pass A: HMMA chunk products, split-bf16 (validated) ----------------
__global__ void __launch_bounds__(32) passA_kernel() {
    __shared__ __align__(16) __nv_bfloat16 Ahs[HH * 64], Als[HH * 64];
    __shared__ __align__(16) __nv_bfloat16 Bhs[HH * 64], Bls[HH * 64];
    __shared__ float ech[CL][HH];
    const unsigned F = 0xffffffffu;
    int lane = threadIdx.x;
    int blk = blockIdx.x, dir = blk >> 9, b = (blk >> 5) & 15, c = blk & 31;
    int t_lo, t_hi, e0;
    if (dir == 0) { t_lo = (c == 0) ? 1 : c * CL; t_hi = c * CL + CL - 1; e0 = t_lo; }
    else { t_lo = c * CL; t_hi = (c == NC - 1) ? TT - 2 : c * CL + CL - 1; e0 = t_lo + 1; }
    int ns = t_hi - t_lo + 1;
    const float* es = g_elep + (size_t)(b * TT + e0) * HH;
    for (int x = lane; x < ns * HH; x += 32) ech[x / HH][x % HH] = es[x];
    __syncwarp(F);
    for (int x = lane; x < HH * HH; x += 32) {
        int i = x / HH, k = x - i * HH;
        float tv = (dir == 0) ? g_trans_prob[k * HH + i] : g_trans_prob[i * HH + k];
        __nv_bfloat16 h = __float2bfloat16(tv);
        __nv_bfloat16 l = __float2bfloat16(tv - __bfloat162float(h));
        uint32_t off = (uint32_t)(i * 128 + k * 2);
        off ^= (off >> 3) & 0x70;
        *(__nv_bfloat16*)((char*)Ahs + off) = h;
        *(__nv_bfloat16*)((char*)Als + off) = l;
    }
    for (int x = lane; x < HH * HH; x += 32) {
        int j = x / HH, i = x - j * HH;
        float v;
        if (dir == 0) v = g_trans_prob[j * HH + i] * ech[0][i];
        else          v = g_trans_prob[i * HH + j] * ech[ns - 1][j] * ech[ns - 2][i];
        __nv_bfloat16 h = __float2bfloat16(v);
        __nv_bfloat16 l = __float2bfloat16(v - __bfloat162float(h));
        uint32_t off = (uint32_t)(j * 128 + i * 2);
        off ^= (off >> 3) & 0x70;
        *(__nv_bfloat16*)((char*)Bhs + off) = h;
        *(__nv_bfloat16*)((char*)Bls + off) = l;
    }
    __syncwarp(F);

    uint32_t ah_b = smem_u32(Ahs), al_b = smem_u32(Als);
    uint32_t bh_b = smem_u32(Bhs), bl_b = smem_u32(Bls);
    const int sub = lane >> 3, l8 = lane & 7;
    const int ar = (sub & 1) * 8 + l8, akb = (sub >> 1) * 16;
    const int br = (sub >> 1) * 8 + l8, bkb = (sub & 1) * 16;
    const int g = lane >> 2, tc = (lane & 3) * 2;

    uint32_t fah[3][3][4], fal[3][3][4];
#pragma unroll
    for (int mi = 0; mi < 3; mi++)
#pragma unroll
        for (int kk = 0; kk < 3; kk++) {
            int r = mi * 16 + ar;
            uint32_t off = (uint32_t)(r * 128) + (uint32_t)((kk * 32 + akb) ^ ((r & 7) << 4));
            LDSM4(fah[mi][kk], ah_b + off);
            LDSM4(fal[mi][kk], al_b + off);
        }

    for (int s = 1; s < ns; s++) {
        float cc[3][6][4];
#pragma unroll
        for (int mi = 0; mi < 3; mi++)
#pragma unroll
            for (int ni = 0; ni < 6; ni++)
#pragma unroll
                for (int q = 0; q < 4; q++) cc[mi][ni][q] = 0.0f;
#pragma unroll
        for (int kk = 0; kk < 3; kk++) {
            uint32_t gh[3][4], gl[3][4];
#pragma unroll
            for (int pi = 0; pi < 3; pi++) {
                int r = pi * 16 + br;
                uint32_t off = (uint32_t)(r * 128) + (uint32_t)((kk * 32 + bkb) ^ ((r & 7) << 4));
                LDSM4(gh[pi], bh_b + off);
                LDSM4(gl[pi], bl_b + off);
            }
#pragma unroll
            for (int mi = 0; mi < 3; mi++)
#pragma unroll
                for (int pi = 0; pi < 3; pi++) {
                    MMAB(cc[mi][2 * pi],     fah[mi][kk], gh[pi][0], gh[pi][1]);
                    MMAB(cc[mi][2 * pi + 1], fah[mi][kk], gh[pi][2], gh[pi][3]);
                    MMAB(cc[mi][2 * pi],     fah[mi][kk], gl[pi][0], gl[pi][1]);
                    MMAB(cc[mi][2 * pi + 1], fah[mi][kk], gl[pi][2], gl[pi][3]);
                    MMAB(cc[mi][2 * pi],     fal[mi][kk], gh[pi][0], gh[pi][1]);
                    MMAB(cc[mi][2 * pi + 1], fal[mi][kk], gh[pi][2], gh[pi][3]);
                }
        }
        int sid = (dir == 0) ? s : (ns - 2 - s);
        float m = 0.0f;
#pragma unroll
        for (int mi = 0; mi < 3; mi++) {
            float slo = 1.0f, shi = 1.0f;
            if (sid >= 0) { slo = ech[sid][mi * 16 + g]; shi = ech[sid][mi * 16 + g + 8]; }
#pragma unroll
            for (int ni = 0; ni < 6; ni++) {
                cc[mi][ni][0] *= slo; cc[mi][ni][1] *= slo;
                cc[mi][ni][2] *= shi; cc[mi][ni][3] *= shi;
                m = fmaxf(m, fmaxf(fmaxf(fabsf(cc[mi][ni][0]), fabsf(cc[mi][ni][1])),
                                   fmaxf(fabsf(cc[mi][ni][2]), fabsf(cc[mi][ni][3]))));
            }
        }
#pragma unroll
        for (int o = 16; o > 0; o >>= 1) m = fmaxf(m, __shfl_xor_sync(F, m, o));
        float rn = 1.0f / m;
        if (s < ns - 1) {
#pragma unroll
            for (int mi = 0; mi < 3; mi++)
#pragma unroll
                for (int ni = 0; ni < 6; ni++)
#pragma unroll
                    for (int q = 0; q < 4; q++) {
                        int ri = mi * 16 + g + ((q >> 1) ? 8 : 0);
                        int cj = ni * 8 + tc + (q & 1);
                        float v = cc[mi][ni][q] * rn;
                        __nv_bfloat16 h = __float2bfloat16(v);
                        __nv_bfloat16 l = __float2bfloat16(v - __bfloat162float(h));
                        uint32_t off = (uint32_t)(cj * 128 + ri * 2);
                        off ^= (off >> 3) & 0x70;
                        *(__nv_bfloat16*)((char*)Bhs + off) = h;
                        *(__nv_bfloat16*)((char*)Bls + off) = l;
                    }
            __syncwarp(F);
        } else {
            float* dst = g_U + (size_t)blk * (HH * HH);
#pragma unroll
            for (int mi = 0; mi < 3; mi++)
#pragma unroll
                for (int ni = 0; ni < 6; ni++) {
                    int r0 = mi * 16 + g, cj = ni * 8 + tc;
                    float2 v0 = {cc[mi][ni][0] * rn, cc[mi][ni][1] * rn};
                    float2 v1 = {cc[mi][ni][2] * rn, cc[mi][ni][3] * rn};
                    *(float2*)&dst[r0 * HH + cj] = v0;
                    *(float2*)&dst[(r0 + 8) * HH + cj] = v1;
                }
        }
    }
}

// ---------------- pass B (validated) ----------------
__global__ void __launch_bounds__(64) passB_kernel() {
    __shared__ __align__(16) float v[HH];
    __shared__ float nv[HH];
    __shared__ float rn;
    int tid = threadIdx.x;
    int dir = blockIdx.x >> 4, b = blockIdx.x & 15;
    bool act = tid < HH;
    float* ent = g_ent + ((size_t)(dir * BB + b) * NC) * HH;
    if (dir == 0) {
        if (act) v[tid] = fexp(g_lp[tid]) * g_elep[(size_t)(b * TT) * HH + tid];
        __syncthreads();
        if (tid == 0) {
            float m = 0;
            for (int k = 0; k < HH; k++) m = fmaxf(m, v[k]);
            rn = 1.0f / m;
        }
        __syncthreads();
        if (act) { v[tid] *= rn; ent[tid] = v[tid]; }
        __syncthreads();
        for (int c = 0; c < NC - 1; c++) {
            const float* U = g_U + (size_t)(b * NC + c) * (HH * HH);
            float s = 0.0f;
            if (act) {
                const float4* u4 = (const float4*)(U + tid * HH);
                const float4* v4 = (const float4*)v;
#pragma unroll
                for (int k = 0; k < 12; k++) {
                    float4 u = u4[k], w = v4[k];
                    s = fmaf(u.x, w.x, s); s = fmaf(u.y, w.y, s);
                    s = fmaf(u.z, w.z, s); s = fmaf(u.w, w.w, s);
                }
            }
            __syncthreads();
            if (act) nv[tid] = s;
            __syncthreads();
            if (tid == 0) {
                float m = 0;
                for (int k = 0; k < HH; k++) m = fmaxf(m, fabsf(nv[k]));
                rn = 1.0f / m;
            }
            __syncthreads();
            if (act) { float x = nv[tid] * rn; v[tid] = x; ent[(size_t)(c + 1) * HH + tid] = x; }
            __syncthreads();
        }
    } else {
        if (act) { v[tid] = 1.0f; ent[(size_t)(NC - 1) * HH + tid] = 1.0f; }
        __syncthreads();
        for (int c = NC - 2; c >= 0; c--) {
            const float* U = g_U + (size_t)(512 + b * NC + (c + 1)) * (HH * HH);
            float s = 0.0f;
            if (act) {
                const float4* u4 = (const float4*)(U + tid * HH);
                const float4* v4 = (const float4*)v;
#pragma unroll
                for (int k = 0; k < 12; k++) {
                    float4 u = u4[k], w = v4[k];
                    s = fmaf(u.x, w.x, s); s = fmaf(u.y, w.y, s);
                    s = fmaf(u.z, w.z, s); s = fmaf(u.w, w.w, s);
                }
            }
            __syncthreads();
            if (act) nv[tid] = s;
            __syncthreads();
            if (tid == 0) {
                float m = 0;
                for (int k = 0; k < HH; k++) m = fmaxf(m, fabsf(nv[k]));
                rn = 1.0f / m;
            }
            __syncthreads();
            if (act) { float x = nv[tid] * rn; v[tid] = x; ent[(size_t)c * HH + tid] = x; }
            __syncthreads();
        }
    }
}

// ---------------- pass C (validated) ----------------
__global__ void __launch_bounds__(64) passC_kernel() {
    __shared__ __align__(16) float cur[HH];
    __shared__ float red2[2];
    const unsigned FULL = 0xffffffffu;
    int tid = threadIdx.x, wid = tid >> 5;
    int blk = blockIdx.x, dir = blk >> 9, b = (blk >> 5) & 15, c = blk & 31;
    bool act = tid < HH;
    float Tc[HH];
    if (act) {
#pragma unroll
        for (int k = 0; k < HH; k++)
            Tc[k] = (dir == 0) ? g_trans_prob[k * HH + tid] : g_trans_prob[tid * HH + k];
    }
    const float* ent = g_ent + ((size_t)(dir * BB + b) * NC + c) * HH;
    float own = act ? ent[tid] : 0.0f;
    if (dir == 0) {
        int tstart = (c == 0) ? 1 : c * CL;
        int tend = c * CL + CL - 1;
        if (c == 0 && act) g_alpha[(size_t)(b * TT) * HH + tid] = own;
        for (int t = tstart; t <= tend; t++) {
            if (act) cur[tid] = own;
            __syncthreads();
            float a = 0.0f;
            if (act) {
                const float4* v4 = (const float4*)cur;
                float p0 = 0, p1 = 0, p2 = 0, p3 = 0;
#pragma unroll
                for (int k = 0; k < 12; k++) {
                    float4 u = v4[k];
                    p0 = fmaf(u.x, Tc[4 * k + 0], p0);
                    p1 = fmaf(u.y, Tc[4 * k + 1], p1);
                    p2 = fmaf(u.z, Tc[4 * k + 2], p2);
                    p3 = fmaf(u.w, Tc[4 * k + 3], p3);
                }
                float el = g_elep[(size_t)(b * TT + t) * HH + tid];
                a = ((p0 + p1) + (p2 + p3)) * el;
                g_alpha[(size_t)(b * TT + t) * HH + tid] = a;
            }
            if ((t & 1) == 0) {
                float s = a;
#pragma unroll
                for (int o = 16; o > 0; o >>= 1) s += __shfl_xor_sync(FULL, s, o);
                if ((tid & 31) == 0) red2[wid] = s;
                __syncthreads();
                a *= 1.0f / (red2[0] + red2[1]);
            }
            own = a;
            __syncthreads();
        }
    } else {
        int thi = (c == NC - 1) ? TT - 2 : c * CL + CL - 1;
        int tlo = c * CL;
        if (c == NC - 1 && act) g_beta[(size_t)(b * TT + TT - 1) * HH + tid] = own;
        for (int t = thi; t >= tlo; t--) {
            if (act) {
                float el = g_elep[(size_t)(b * TT + t + 1) * HH + tid];
                cur[tid] = el * own;
            }
            __syncthreads();
            float a = 0.0f;
            if (act) {
                const float4* v4 = (const float4*)cur;
                float p0 = 0, p1 = 0, p2 = 0, p3 = 0;
#pragma unroll
                for (int k = 0; k < 12; k++) {
                    float4 u = v4[k];
                    p0 = fmaf(u.x, Tc[4 * k + 0], p0);
                    p1 = fmaf(u.y, Tc[4 * k + 1], p1);
                    p2 = fmaf(u.z, Tc[4 * k + 2], p2);
                    p3 = fmaf(u.w, Tc[4 * k + 3], p3);
                }
                a = (p0 + p1) + (p2 + p3);
                g_beta[(size_t)(b * TT + t) * HH + tid] = a;
            }
            if ((t & 1) == 0) {
                float s = a;
#pragma unroll
                for (int o = 16; o > 0; o >>= 1) s += __shfl_xor_sync(FULL, s, o);
                if ((tid & 31) == 0) red2[wid] = s;
                __syncthreads();
                a *= 1.0f / (red2[0] + red2[1]);
            }
            own = a;
            __syncthreads();
        }
    }
}

// ---------------- final: 4 t per block (validated round 15) ----------------
__global__ void __launch_bounds__(256) final_kernel(const int* __restrict__ seq) {
    __shared__ float lt[HH * HH];
    __shared__ float tp[HH * HH];
    __shared__ float sA[HH], sU[HH], sG[HH], sL[HH];
    __shared__ float red[32];
    int tid = threadIdx.x;
    int b = blockIdx.x >> 7;
    int t0 = (blockIdx.x & 127) * 4;
    int len = seq[b];

    for (int i = tid; i < HH * HH; i += 256) {
        lt[i] = g_log_trans[i];
        tp[i] = g_trans_prob[i];
    }
    __syncthreads();

    for (int q4 = 0; q4 < 4; q4++) {
        int t = t0 + q4;
        int bt = b * TT + t;
        if (t >= len) {
            if (tid == 0) g_partial[bt] = 0.0f;
            continue;
        }
        bool do_xi = (t >= 1);
        if (tid < HH) {
            int tb = (t + TT - len) & (TT - 1);
            float br = g_beta[(size_t)(b * TT + tb) * HH + tid];
            float at = g_alpha[(size_t)bt * HH + tid];
            float lpv = g_lep[(size_t)bt * HH + tid];
            float el = g_elep[(size_t)bt * HH + tid];
            sG[tid] = at * br;
            sU[tid] = el * br;
            sL[tid] = lpv;
            sA[tid] = (t > 0) ? g_alpha[(size_t)(bt - 1) * HH + tid] : 0.0f;
        }
        __syncthreads();

        float e = (tid < HH) ? sG[tid] : 0.0f;
        float Z = blockSum256(e, red);
        float E = blockSum256(e * ((tid < HH) ? sL[tid] : 0.0f), red);
        float total = E / Z;
        if (t == 0) {
            float P = blockSum256(e * ((tid < HH) ? g_lp[tid] : 0.0f), red);
            total += P / Z;
        }
        if (do_xi) {
            float z = 0.0f, w = 0.0f;
            for (int idx = tid; idx < HH * HH; idx += 256) {
                int i = idx / HH, j = idx - i * HH;
                float val = tp[idx] * sA[i] * sU[j];
                z += val;
                w = fmaf(val, lt[idx], w);
            }
            float Z2 = blockSum256(z, red);
            float W2 = blockSum256(w, red);
            total += W2 / Z2;
        }
        if (tid == 0) g_partial[bt] = total;
        __syncthreads();
    }
}

__global__ void __launch_bounds__(256) reduce_kernel(float* __restrict__ out) {
    __shared__ float red[256];
    int tid = threadIdx.x;
    float s = 0.0f;
    for (int i = tid; i < MTOT; i += 256) s += g_partial[i];
    red[tid] = s;
    __syncthreads();
    for (int off = 128; off > 0; off >>= 1) {
        if (tid < off) red[tid] += red[tid + off];
        __syncthreads();
    }
    if (tid == 0) out[0] = red[0] * (1.0f / (float)BB);
}

extern "C" void kernel_launch(void* const* d_in, const int* in_sizes, int n_in,
                              void* d_out, int out_size) {
    const float* emb  = (const float*)d_in[0];
    const float* obs  = (const float*)d_in[1];
    const float* sp   = (const float*)d_in[2];
    const float* ut   = (const float*)d_in[3];
    const float* ue   = (const float*)d_in[4];
    const float* Wm   = (const float*)d_in[5];
    const float* bias = (const float*)d_in[6];
    const int*   seq  = (const int*)d_in[7];
    float* out = (float*)d_out;

    cudaFuncSetAttribute(mma_fused_kernel, cudaFuncAttributeMaxDynamicSharedMemorySize, GEMM_SMEM);

    init_kernel<<<CONV_BLOCKS + 1, 256>>>(emb, Wm, sp, ut, ue);   // 1
    dim3 ggrid(NN / 96, MTOT / 128);
    mma_fused_kernel<<<ggrid, 256, GEMM_SMEM>>>(bias, obs);       // 2
    combine_kernel<<<(MTOT * HH + 255) / 256, 256>>>();           // 3
    passA_kernel<<<1024, 32>>>();                                 // 4
    passB_kernel<<<32, 64>>>();                                   // 5
    passC_kernel<<<1024, 64>>>();                                 // 6
    final_kernel<<<MTOT / 4, 256>>>(seq);                         // 7
    reduce_kernel<<<1, 256>>>(out);                               // 8
}